// round 7
// baseline (speedup 1.0000x reference)
#include <cuda_runtime.h>
#include <cuda_bf16.h>

// MeanAggregator: out[r,:] = mean over UNIQUE neighbors c of row r of embed[c,:]
// row_idx sorted ascending. D = 300 floats = 75 float4. Warp-per-row.
// Set semantics via GATHER-ALL + SUBTRACT-DUPLICATES; duplicate detection is
// deferred until after the gather loop so the load pipeline starts immediately.

#define AGG_D4   75
#define AGG_MAXL 96            // fast-path cap: 3 chunks (L ~ Poisson(32), max ~70)
#define AGG_MAXB 65536
#define ROWS_PB  8             // warps (rows) per 256-thread block

__device__ int g_row_start[AGG_MAXB + 1];

// CSR row pointers by diff-scatter over the sorted row_idx (O(E), contiguous loads).
__global__ void build_row_starts(const int* __restrict__ row_idx, int E, int B) {
    int i = blockIdx.x * blockDim.x + threadIdx.x;
    if (i > E) return;
    if (i == 0) {
        int cur = row_idx[0];
        for (int v = 0; v <= cur; ++v) g_row_start[v] = 0;
    } else if (i == E) {
        int prev = row_idx[E - 1];
        for (int v = prev + 1; v <= B; ++v) g_row_start[v] = E;
    } else {
        int prev = row_idx[i - 1];
        int cur  = row_idx[i];
        for (int v = prev + 1; v <= cur; ++v) g_row_start[v] = i;
    }
}

__global__ __launch_bounds__(ROWS_PB * 32) void mean_agg_kernel(
    const int*    __restrict__ col_idx,
    const float4* __restrict__ embed4,   // [U, 75]
    float4*       __restrict__ out4,     // [B, 75]
    int B)
{
    const int w    = threadIdx.x >> 5;
    const int lane = threadIdx.x & 31;
    const int r    = blockIdx.x * ROWS_PB + w;
    if (r >= B) return;                       // warp-uniform

    const int start = g_row_start[r];
    const int L     = g_row_start[r + 1] - start;

    __shared__ int s_col[ROWS_PB][AGG_MAXL];
    int* sc = s_col[w];

    float4 a0 = make_float4(0.f, 0.f, 0.f, 0.f);
    float4 a1 = a0, a2 = a0;
    const unsigned lt   = (1u << lane) - 1u;
    const bool     has3 = (lane < AGG_D4 - 64);
    const float4* __restrict__ e = embed4 + lane;
    int Lu = 0;

    if (L <= AGG_MAXL) {
        // ---- 3 independent coalesced chunk loads of col indices ----
        const int j1 = 32 + lane, j2 = 64 + lane;
        int c0 = (lane < L) ? col_idx[start + lane] : -(lane + 1);
        int c1 = (j1   < L) ? col_idx[start + j1]   : -(lane + 1);
        int c2 = (j2   < L) ? col_idx[start + j2]   : -(lane + 1);
        sc[lane] = c0;
        if (j1 < L) sc[j1] = c1;
        if (j2 < L) sc[j2] = c2;
        __syncwarp();

        // ---- main gather over ALL L entries (dups included): unroll-8,
        //      24 independent LDG.128 in flight per warp ----
        int j = 0;
        for (; j + 8 <= L; j += 8) {
            const float4* p0 = e + (size_t)sc[j]     * AGG_D4;
            const float4* p1 = e + (size_t)sc[j + 1] * AGG_D4;
            const float4* p2 = e + (size_t)sc[j + 2] * AGG_D4;
            const float4* p3 = e + (size_t)sc[j + 3] * AGG_D4;
            const float4* p4 = e + (size_t)sc[j + 4] * AGG_D4;
            const float4* p5 = e + (size_t)sc[j + 5] * AGG_D4;
            const float4* p6 = e + (size_t)sc[j + 6] * AGG_D4;
            const float4* p7 = e + (size_t)sc[j + 7] * AGG_D4;
            float4 x0 = p0[0],  x1 = p1[0],  x2 = p2[0],  x3 = p3[0];
            float4 x4 = p4[0],  x5 = p5[0],  x6 = p6[0],  x7 = p7[0];
            float4 y0 = p0[32], y1 = p1[32], y2 = p2[32], y3 = p3[32];
            float4 y4 = p4[32], y5 = p5[32], y6 = p6[32], y7 = p7[32];
            if (has3) {
                float4 z0 = p0[64], z1 = p1[64], z2 = p2[64], z3 = p3[64];
                float4 z4 = p4[64], z5 = p5[64], z6 = p6[64], z7 = p7[64];
                a2.x += (z0.x + z1.x + z2.x + z3.x) + (z4.x + z5.x + z6.x + z7.x);
                a2.y += (z0.y + z1.y + z2.y + z3.y) + (z4.y + z5.y + z6.y + z7.y);
                a2.z += (z0.z + z1.z + z2.z + z3.z) + (z4.z + z5.z + z6.z + z7.z);
                a2.w += (z0.w + z1.w + z2.w + z3.w) + (z4.w + z5.w + z6.w + z7.w);
            }
            a0.x += (x0.x + x1.x + x2.x + x3.x) + (x4.x + x5.x + x6.x + x7.x);
            a0.y += (x0.y + x1.y + x2.y + x3.y) + (x4.y + x5.y + x6.y + x7.y);
            a0.z += (x0.z + x1.z + x2.z + x3.z) + (x4.z + x5.z + x6.z + x7.z);
            a0.w += (x0.w + x1.w + x2.w + x3.w) + (x4.w + x5.w + x6.w + x7.w);
            a1.x += (y0.x + y1.x + y2.x + y3.x) + (y4.x + y5.x + y6.x + y7.x);
            a1.y += (y0.y + y1.y + y2.y + y3.y) + (y4.y + y5.y + y6.y + y7.y);
            a1.z += (y0.z + y1.z + y2.z + y3.z) + (y4.z + y5.z + y6.z + y7.z);
            a1.w += (y0.w + y1.w + y2.w + y3.w) + (y4.w + y5.w + y6.w + y7.w);
        }
        for (; j + 4 <= L; j += 4) {
            const float4* p0 = e + (size_t)sc[j]     * AGG_D4;
            const float4* p1 = e + (size_t)sc[j + 1] * AGG_D4;
            const float4* p2 = e + (size_t)sc[j + 2] * AGG_D4;
            const float4* p3 = e + (size_t)sc[j + 3] * AGG_D4;
            float4 x0 = p0[0],  x1 = p1[0],  x2 = p2[0],  x3 = p3[0];
            float4 y0 = p0[32], y1 = p1[32], y2 = p2[32], y3 = p3[32];
            if (has3) {
                float4 z0 = p0[64], z1 = p1[64], z2 = p2[64], z3 = p3[64];
                a2.x += z0.x + z1.x + z2.x + z3.x;
                a2.y += z0.y + z1.y + z2.y + z3.y;
                a2.z += z0.z + z1.z + z2.z + z3.z;
                a2.w += z0.w + z1.w + z2.w + z3.w;
            }
            a0.x += x0.x + x1.x + x2.x + x3.x;
            a0.y += x0.y + x1.y + x2.y + x3.y;
            a0.z += x0.z + x1.z + x2.z + x3.z;
            a0.w += x0.w + x1.w + x2.w + x3.w;
            a1.x += y0.x + y1.x + y2.x + y3.x;
            a1.y += y0.y + y1.y + y2.y + y3.y;
            a1.z += y0.z + y1.z + y2.z + y3.z;
            a1.w += y0.w + y1.w + y2.w + y3.w;
        }
        for (; j < L; ++j) {
            const float4* p = e + (size_t)sc[j] * AGG_D4;
            float4 x = p[0], y = p[32];
            if (has3) {
                float4 z = p[64];
                a2.x += z.x; a2.y += z.y; a2.z += z.z; a2.w += z.w;
            }
            a0.x += x.x; a0.y += x.y; a0.z += x.z; a0.w += x.w;
            a1.x += y.x; a1.y += y.y; a1.z += y.z; a1.w += y.w;
        }

        // ---- duplicate detection AFTER the gather (overlaps last batch) ----
        unsigned p0m = __match_any_sync(0xffffffffu, c0);
        bool d0 = (lane < L) && ((p0m & lt) != 0);
        bool d1 = false, d2 = false;
        if (L > 32) {
            unsigned p1m = __match_any_sync(0xffffffffu, c1);
            d1 = (j1 < L) && ((p1m & lt) != 0);
            if (!d1 && j1 < L) {
                for (int i = 0; i < 32; ++i)
                    if (sc[i] == c1) { d1 = true; break; }
            }
            if (L > 64) {
                unsigned p2m = __match_any_sync(0xffffffffu, c2);
                d2 = (j2 < L) && ((p2m & lt) != 0);
                if (!d2 && j2 < L) {
                    for (int i = 0; i < 64; ++i)
                        if (sc[i] == c2) { d2 = true; break; }
                }
            }
        }
        const unsigned m0 = __ballot_sync(0xffffffffu, d0);
        const unsigned m1 = __ballot_sync(0xffffffffu, d1);
        const unsigned m2 = __ballot_sync(0xffffffffu, d2);
        Lu = L - (__popc(m0) + __popc(m1) + __popc(m2));

        // ---- subtract duplicate occurrences (almost always all-zero masks) ----
        if (m0 | m1 | m2) {
            unsigned masks[3] = { m0, m1, m2 };
            #pragma unroll
            for (int k = 0; k < 3; ++k) {
                unsigned m = masks[k];
                while (m) {
                    int b = __ffs(m) - 1; m &= m - 1;
                    const float4* p = e + (size_t)sc[k * 32 + b] * AGG_D4;
                    float4 x = p[0], y = p[32];
                    if (has3) {
                        float4 z = p[64];
                        a2.x -= z.x; a2.y -= z.y; a2.z -= z.z; a2.w -= z.w;
                    }
                    a0.x -= x.x; a0.y -= x.y; a0.z -= x.z; a0.w -= x.w;
                    a1.x -= y.x; a1.y -= y.y; a1.z -= y.z; a1.w -= y.w;
                }
            }
        }
    } else {
        // Unreachable-for-this-data fallback: O(L^2) global dedup, direct accumulate.
        for (int j = 0; j < L; ++j) {
            int c = col_idx[start + j];
            bool valid = true;
            for (int i = 0; i < j; ++i)
                if (col_idx[start + i] == c) { valid = false; break; }
            if (!valid) continue;
            ++Lu;
            const float4* p = e + (size_t)c * AGG_D4;
            float4 x = p[0], y = p[32];
            if (has3) {
                float4 z = p[64];
                a2.x += z.x; a2.y += z.y; a2.z += z.z; a2.w += z.w;
            }
            a0.x += x.x; a0.y += x.y; a0.z += x.z; a0.w += x.w;
            a1.x += y.x; a1.y += y.y; a1.z += y.z; a1.w += y.w;
        }
    }

    const float inv = 1.0f / fmaxf((float)Lu, 1e-8f);
    float4* o = out4 + (size_t)r * AGG_D4 + lane;
    float4 t;
    t.x = a0.x * inv; t.y = a0.y * inv; t.z = a0.z * inv; t.w = a0.w * inv;
    o[0] = t;
    t.x = a1.x * inv; t.y = a1.y * inv; t.z = a1.z * inv; t.w = a1.w * inv;
    o[32] = t;
    if (has3) {
        t.x = a2.x * inv; t.y = a2.y * inv; t.z = a2.z * inv; t.w = a2.w * inv;
        o[64] = t;
    }
}

extern "C" void kernel_launch(void* const* d_in, const int* in_sizes, int n_in,
                              void* d_out, int out_size) {
    const int*   row_idx = (const int*)  d_in[0];
    const int*   col_idx = (const int*)  d_in[1];
    const float* embed   = (const float*)d_in[2];
    float*       out     = (float*)      d_out;

    const int E = in_sizes[0];
    const int B = out_size / 300;

    build_row_starts<<<(E + 1 + 255) / 256, 256>>>(row_idx, E, B);
    mean_agg_kernel<<<(B + ROWS_PB - 1) / ROWS_PB, ROWS_PB * 32>>>(
        col_idx, (const float4*)embed, (float4*)out, B);
}

// round 8
// speedup vs baseline: 1.1023x; 1.1023x over previous
#include <cuda_runtime.h>
#include <cuda_bf16.h>

// MeanAggregator: out[r,:] = mean over UNIQUE neighbors c of row r of embed[c,:]
// row_idx sorted ascending. D = 300 floats = 75 float4.
// Design: one warp per (row, slot). slot 0 -> float4 lane, slot 1 -> lane+32,
// slot 2 -> lane+64 (11 lanes). 3x warp parallelism vs warp-per-row, identical
// coalescing (same warp-wide LDG.128 footprints). Set semantics via GATHER-ALL
// + SUBTRACT-DUPLICATES with dup detection deferred past the gather loop.
// Each warp is fully independent -> no cross-warp sync; deterministic.

#define AGG_D4   75
#define AGG_MAXL 96            // fast-path cap: 3 chunks (L ~ Poisson(32), max ~70)
#define AGG_MAXB 65536
#define WARPS_PB 8             // 256-thread blocks

__device__ int g_row_start[AGG_MAXB + 1];

// CSR row pointers by diff-scatter over the sorted row_idx (O(E), contiguous loads).
__global__ void build_row_starts(const int* __restrict__ row_idx, int E, int B) {
    int i = blockIdx.x * blockDim.x + threadIdx.x;
    if (i > E) return;
    if (i == 0) {
        int cur = row_idx[0];
        for (int v = 0; v <= cur; ++v) g_row_start[v] = 0;
    } else if (i == E) {
        int prev = row_idx[E - 1];
        for (int v = prev + 1; v <= B; ++v) g_row_start[v] = E;
    } else {
        int prev = row_idx[i - 1];
        int cur  = row_idx[i];
        for (int v = prev + 1; v <= cur; ++v) g_row_start[v] = i;
    }
}

__global__ __launch_bounds__(WARPS_PB * 32) void mean_agg_kernel(
    const int*    __restrict__ col_idx,
    const float4* __restrict__ embed4,   // [U, 75]
    float4*       __restrict__ out4,     // [B, 75]
    int B)
{
    const int w    = threadIdx.x >> 5;
    const int lane = threadIdx.x & 31;
    const int gw   = blockIdx.x * WARPS_PB + w;   // global warp id
    const int r    = gw / 3;                      // row
    const int slot = gw - r * 3;                  // LDG slot 0/1/2
    if (r >= B) return;                           // warp-uniform

    const int  d4   = slot * 32 + lane;           // my float4 index in [0,75)
    const bool act  = (d4 < AGG_D4);              // slot 2: lanes 0..10 only

    const int start = g_row_start[r];
    const int L     = g_row_start[r + 1] - start;

    __shared__ int s_col[WARPS_PB][AGG_MAXL];
    int* sc = s_col[w];

    float4 acc = make_float4(0.f, 0.f, 0.f, 0.f);
    const unsigned lt = (1u << lane) - 1u;
    const float4* __restrict__ e = embed4 + d4;
    int Lu = 0;

    if (L <= AGG_MAXL) {
        // ---- 3 independent coalesced chunk loads of col indices ----
        const int j1 = 32 + lane, j2 = 64 + lane;
        int c0 = (lane < L) ? col_idx[start + lane] : -(lane + 1);
        int c1 = (j1   < L) ? col_idx[start + j1]   : -(lane + 1);
        int c2 = (j2   < L) ? col_idx[start + j2]   : -(lane + 1);
        sc[lane] = c0;
        if (j1 < L) sc[j1] = c1;
        if (j2 < L) sc[j2] = c2;
        __syncwarp();

        // ---- main gather over ALL L entries (dups included): unroll-8,
        //      8 independent LDG.128 in flight, 1 LDG per neighbor ----
        if (act) {
            int j = 0;
            for (; j + 8 <= L; j += 8) {
                float4 v0 = e[(size_t)sc[j]     * AGG_D4];
                float4 v1 = e[(size_t)sc[j + 1] * AGG_D4];
                float4 v2 = e[(size_t)sc[j + 2] * AGG_D4];
                float4 v3 = e[(size_t)sc[j + 3] * AGG_D4];
                float4 v4 = e[(size_t)sc[j + 4] * AGG_D4];
                float4 v5 = e[(size_t)sc[j + 5] * AGG_D4];
                float4 v6 = e[(size_t)sc[j + 6] * AGG_D4];
                float4 v7 = e[(size_t)sc[j + 7] * AGG_D4];
                acc.x += (v0.x + v1.x + v2.x + v3.x) + (v4.x + v5.x + v6.x + v7.x);
                acc.y += (v0.y + v1.y + v2.y + v3.y) + (v4.y + v5.y + v6.y + v7.y);
                acc.z += (v0.z + v1.z + v2.z + v3.z) + (v4.z + v5.z + v6.z + v7.z);
                acc.w += (v0.w + v1.w + v2.w + v3.w) + (v4.w + v5.w + v6.w + v7.w);
            }
            for (; j + 4 <= L; j += 4) {
                float4 v0 = e[(size_t)sc[j]     * AGG_D4];
                float4 v1 = e[(size_t)sc[j + 1] * AGG_D4];
                float4 v2 = e[(size_t)sc[j + 2] * AGG_D4];
                float4 v3 = e[(size_t)sc[j + 3] * AGG_D4];
                acc.x += v0.x + v1.x + v2.x + v3.x;
                acc.y += v0.y + v1.y + v2.y + v3.y;
                acc.z += v0.z + v1.z + v2.z + v3.z;
                acc.w += v0.w + v1.w + v2.w + v3.w;
            }
            for (; j < L; ++j) {
                float4 v = e[(size_t)sc[j] * AGG_D4];
                acc.x += v.x; acc.y += v.y; acc.z += v.z; acc.w += v.w;
            }
        }

        // ---- duplicate detection AFTER the gather (all lanes participate) ----
        unsigned p0m = __match_any_sync(0xffffffffu, c0);
        bool d0 = (lane < L) && ((p0m & lt) != 0);
        bool d1 = false, d2 = false;
        if (L > 32) {
            unsigned p1m = __match_any_sync(0xffffffffu, c1);
            d1 = (j1 < L) && ((p1m & lt) != 0);
            if (!d1 && j1 < L) {
                for (int i = 0; i < 32; ++i)
                    if (sc[i] == c1) { d1 = true; break; }
            }
            if (L > 64) {
                unsigned p2m = __match_any_sync(0xffffffffu, c2);
                d2 = (j2 < L) && ((p2m & lt) != 0);
                if (!d2 && j2 < L) {
                    for (int i = 0; i < 64; ++i)
                        if (sc[i] == c2) { d2 = true; break; }
                }
            }
        }
        const unsigned m0 = __ballot_sync(0xffffffffu, d0);
        const unsigned m1 = __ballot_sync(0xffffffffu, d1);
        const unsigned m2 = __ballot_sync(0xffffffffu, d2);
        Lu = L - (__popc(m0) + __popc(m1) + __popc(m2));

        // ---- subtract duplicate occurrences (almost always all-zero masks) ----
        if (act && (m0 | m1 | m2)) {
            unsigned masks[3] = { m0, m1, m2 };
            #pragma unroll
            for (int k = 0; k < 3; ++k) {
                unsigned m = masks[k];
                while (m) {
                    int b = __ffs(m) - 1; m &= m - 1;
                    float4 v = e[(size_t)sc[k * 32 + b] * AGG_D4];
                    acc.x -= v.x; acc.y -= v.y; acc.z -= v.z; acc.w -= v.w;
                }
            }
        }
    } else {
        // Unreachable-for-this-data fallback: O(L^2) global dedup, direct accumulate.
        for (int j = 0; j < L; ++j) {
            int c = col_idx[start + j];
            bool valid = true;
            for (int i = 0; i < j; ++i)
                if (col_idx[start + i] == c) { valid = false; break; }
            if (!valid) continue;
            ++Lu;
            if (act) {
                float4 v = e[(size_t)c * AGG_D4];
                acc.x += v.x; acc.y += v.y; acc.z += v.z; acc.w += v.w;
            }
        }
    }

    if (act) {
        const float inv = 1.0f / fmaxf((float)Lu, 1e-8f);
        float4 t;
        t.x = acc.x * inv; t.y = acc.y * inv; t.z = acc.z * inv; t.w = acc.w * inv;
        out4[(size_t)r * AGG_D4 + d4] = t;
    }
}

extern "C" void kernel_launch(void* const* d_in, const int* in_sizes, int n_in,
                              void* d_out, int out_size) {
    const int*   row_idx = (const int*)  d_in[0];
    const int*   col_idx = (const int*)  d_in[1];
    const float* embed   = (const float*)d_in[2];
    float*       out     = (float*)      d_out;

    const int E = in_sizes[0];
    const int B = out_size / 300;

    const int total_warps = 3 * B;
    build_row_starts<<<(E + 1 + 255) / 256, 256>>>(row_idx, E, B);
    mean_agg_kernel<<<(total_warps + WARPS_PB - 1) / WARPS_PB, WARPS_PB * 32>>>(
        col_idx, (const float4*)embed, (float4*)out, B);
}